// round 11
// baseline (speedup 1.0000x reference)
#include <cuda_runtime.h>
#include <math.h>
#include <stdint.h>

#define BB 128
#define VV 128000
#define VV4 (VV / 4)
#define NBINS 16384
#define BPT (NBINS / NTH)         // bins per thread = 16
#define BIN_SCALE 256.0f          // bin width 1/256 over absolute x
#define XOFF 32.0f                // bins cover x in [-32, 32)
#define CAND_CAP 2048
#define NTH 1024
#define FINFO_MIN -3.4028234663852886e38f

#define CNT_SHIFT 47
#define MASK47 ((1ull << 47) - 1ull)
#define SCALE29 536870912.0f      // 2^29
#define INV29 (1.0 / 536870912.0)

struct Smem {
    unsigned long long  hist[NBINS];       // packed cnt<<47 | fix29(exp rel to bin edge)
    unsigned long long  cand[CAND_CAP];    // top-k candidates: key = flip(x)<<32 | ~idx
    float               pbin[CAND_CAP];    // values in the top-p cutoff bin
    double              bufA[CAND_CAP];
    double              bufB[CAND_CAP];
    unsigned long long  scan64[NTH];
    float               redf[NTH];
    // scalars
    int   cb_p, cb_k;                      // ABSOLUTE bin indices of cutoff bins
    unsigned int candCount, pbinCount;
    int   cntA;
    double A_cbp_sh;
    float logS;
    float xmin_kept;
    int   token;
    float xtok;
};

__device__ __forceinline__ unsigned flipf(float f) {
    unsigned u = __float_as_uint(f);
    return u ^ ((u >> 31) ? 0xFFFFFFFFu : 0x80000000u);
}
__device__ __forceinline__ float unflipf(unsigned u) {
    unsigned b = u ^ ((u & 0x80000000u) ? 0x80000000u : 0xFFFFFFFFu);
    return __uint_as_float(b);
}
__device__ __forceinline__ int binabs(float x) {
    int b = (int)((x + XOFF) * BIN_SCALE);
    return b < 0 ? 0 : (b > NBINS - 1 ? NBINS - 1 : b);
}

// Inclusive double scan over a[0..n2), n2 = pow2 <= 2048.
// ALL NTH threads must call; barriers are unconditional.
__device__ void scan_inclusive(double* a, int n2) {
    int tid = threadIdx.x;
    for (int off = 1; off < n2; off <<= 1) {
        double v0 = 0.0, v1 = 0.0;
        int i0 = tid, i1 = tid + NTH;
        bool h0 = i0 < n2, h1 = i1 < n2;
        if (h0) { v0 = a[i0]; if (i0 >= off) v0 += a[i0 - off]; }
        if (h1) { v1 = a[i1]; if (i1 >= off) v1 += a[i1 - off]; }
        __syncthreads();
        if (h0) a[i0] = v0;
        if (h1) a[i1] = v1;
        __syncthreads();
    }
}

__global__ void __launch_bounds__(NTH, 1)
sampler_kernel(const float* __restrict__ logits,
               const float* __restrict__ temps,
               const int*   __restrict__ topks,
               const float* __restrict__ topps,
               const float* __restrict__ minps,
               const float* __restrict__ us,
               float* __restrict__ out)
{
    extern __shared__ char smem_raw[];
    Smem* sm = reinterpret_cast<Smem*>(smem_raw);
    const int row = blockIdx.x;
    const int tid = threadIdx.x;
    const int lane = tid & 31;
    const int wid  = tid >> 5;
    const float* __restrict__ rowp = logits + (size_t)row * VV;
    const float4* __restrict__ rowp4 = reinterpret_cast<const float4*>(rowp);

    const float temp  = temps[row];
    const float invt  = 1.0f / temp;       // x = logit * invt, used identically in every pass
    const int   K     = topks[row];
    const float top_p = topps[row];
    const float min_p = minps[row];
    const float u     = us[row];

    // -------- init --------
    for (int i = tid; i < NBINS; i += NTH) sm->hist[i] = 0ull;
    if (tid == 0) {
        sm->candCount = 0u; sm->pbinCount = 0u; sm->cntA = 0;
        sm->cb_p = 0; sm->cb_k = 0; sm->A_cbp_sh = 0.0;
    }
    __syncthreads();

    // -------- fused pass 1+2: absolute-bin packed histogram + running max --------
    float mt = -INFINITY;
    for (int i = tid; i < VV4; i += NTH) {
        float4 v = rowp4[i];
        float x0 = v.x * invt, x1 = v.y * invt, x2 = v.z * invt, x3 = v.w * invt;
        mt = fmaxf(mt, fmaxf(fmaxf(x0, x1), fmaxf(x2, x3)));
        int b0 = binabs(x0), b1 = binabs(x1), b2 = binabs(x2), b3 = binabs(x3);
        // e_rel = exp(x - left_edge(bin)) in [1, 1.004] (bottom-clamped bins < 1)
        float e0 = __expf(x0 - ((float)b0 * (1.0f / BIN_SCALE) - XOFF));
        float e1 = __expf(x1 - ((float)b1 * (1.0f / BIN_SCALE) - XOFF));
        float e2 = __expf(x2 - ((float)b2 * (1.0f / BIN_SCALE) - XOFF));
        float e3 = __expf(x3 - ((float)b3 * (1.0f / BIN_SCALE) - XOFF));
        atomicAdd(&sm->hist[b0], (1ull << CNT_SHIFT) + (unsigned long long)(e0 * SCALE29 + 0.5f));
        atomicAdd(&sm->hist[b1], (1ull << CNT_SHIFT) + (unsigned long long)(e1 * SCALE29 + 0.5f));
        atomicAdd(&sm->hist[b2], (1ull << CNT_SHIFT) + (unsigned long long)(e2 * SCALE29 + 0.5f));
        atomicAdd(&sm->hist[b3], (1ull << CNT_SHIFT) + (unsigned long long)(e3 * SCALE29 + 0.5f));
    }
    // max reduce
#pragma unroll
    for (int o = 16; o > 0; o >>= 1) mt = fmaxf(mt, __shfl_xor_sync(0xFFFFFFFFu, mt, o));
    if (lane == 0) sm->redf[wid] = mt;
    __syncthreads();
    if (tid < 32) {
        float v = sm->redf[tid];
#pragma unroll
        for (int o = 16; o > 0; o >>= 1) v = fmaxf(v, __shfl_xor_sync(0xFFFFFFFFu, v, o));
        if (tid == 0) sm->redf[0] = v;
    }
    __syncthreads();
    const float m = sm->redf[0];
    __syncthreads();

    // -------- per-thread local sums over 16 bins in DESCENDING-x order --------
    // thread tid owns rb in [tid*16, tid*16+16), absolute bin = NBINS-1-rb
    const int base = tid * BPT;
    const double STEPD = exp(-1.0 / 256.0);
    unsigned lc[BPT];
    double   le[BPT];
    {
        unsigned crun = 0; double erun = 0.0;
        int b_abs0 = NBINS - 1 - base;
        double w = exp((double)b_abs0 * (1.0 / 256.0) - (double)XOFF - (double)m);
#pragma unroll
        for (int j = 0; j < BPT; j++) {
            unsigned long long raw = sm->hist[b_abs0 - j];
            crun += (unsigned)(raw >> CNT_SHIFT);
            erun += (double)(raw & MASK47) * INV29 * w;
            lc[j] = crun;  le[j] = erun;
            w *= STEPD;
        }
        sm->scan64[tid] = (unsigned long long)crun;
        sm->bufA[tid]   = erun;
    }
    __syncthreads();
    // combined block scan over thread totals (counts + mass), one barrier pair/round
    for (int off = 1; off < NTH; off <<= 1) {
        unsigned long long cv = sm->scan64[tid]; double ev = sm->bufA[tid];
        unsigned long long ca = 0ull; double ea = 0.0;
        if (tid >= off) { ca = sm->scan64[tid - off]; ea = sm->bufA[tid - off]; }
        __syncthreads();
        sm->scan64[tid] = cv + ca;
        sm->bufA[tid]   = ev + ea;
        __syncthreads();
    }
    const double Zh = sm->bufA[NTH - 1];
    const double P  = (double)top_p * Zh;              // top-p mass threshold (exp units rel. m)

    // -------- locate cutoff bins (descending-x order) --------
    {
        unsigned cex = (unsigned)sm->scan64[tid] - lc[BPT - 1];
        double   eex = sm->bufA[tid] - le[BPT - 1];
        int b_abs0 = NBINS - 1 - base;
#pragma unroll
        for (int j = 0; j < BPT; j++) {
            unsigned cA = cex + (j ? lc[j - 1] : 0u);
            unsigned cI = cex + lc[j];
            double   A  = eex + (j ? le[j - 1] : 0.0);
            double   I  = eex + le[j];
            if (A <= P && P < I) { sm->cb_p = b_abs0 - j; sm->A_cbp_sh = A; }
            if (cA < (unsigned)K && (unsigned)K <= cI) sm->cb_k = b_abs0 - j;
        }
    }
    __syncthreads();
    const int    cb_p  = sm->cb_p;      // absolute bin of top-p cutoff
    const int    cb_k  = sm->cb_k;      // absolute bin of top-k cutoff
    const double A_cbp = sm->A_cbp_sh;
    __syncthreads();

    // -------- pass 3: collect top-k candidates and top-p cutoff-bin members --------
    for (int i = tid; i < VV4; i += NTH) {
        float4 v = rowp4[i];
        float xs[4];
        xs[0] = v.x * invt; xs[1] = v.y * invt; xs[2] = v.z * invt; xs[3] = v.w * invt;
#pragma unroll
        for (int j = 0; j < 4; j++) {
            float x = xs[j];
            int b = binabs(x);
            if (b >= cb_k) {
                unsigned p = atomicAdd(&sm->candCount, 1u);
                if (p < CAND_CAP) {
                    unsigned fu = flipf(x);
                    unsigned gidx = (unsigned)(4 * i + j);
                    sm->cand[p] = ((unsigned long long)fu << 32) | (unsigned)(~gidx);
                }
            }
            if (b == cb_p) {
                unsigned q = atomicAdd(&sm->pbinCount, 1u);
                if (q < CAND_CAP) sm->pbin[q] = x;
            }
        }
    }
    __syncthreads();
    const int C   = (int)min(sm->candCount, (unsigned)CAND_CAP);
    const int npb = (int)min(sm->pbinCount, (unsigned)CAND_CAP);

    // -------- bitonic sort candidates descending (value desc, index asc) --------
    int n2 = 1; while (n2 < C) n2 <<= 1;
    for (int i = C + tid; i < n2; i += NTH) sm->cand[i] = 0ull;
    __syncthreads();
    for (int k = 2; k <= n2; k <<= 1)
        for (int j = k >> 1; j > 0; j >>= 1) {
            for (int idx = tid; idx < n2; idx += NTH) {
                int ixj = idx ^ j;
                if (ixj > idx) {
                    unsigned long long a = sm->cand[idx], b2 = sm->cand[ixj];
                    bool up = ((idx & k) == 0);
                    if (up ? (a < b2) : (a > b2)) { sm->cand[idx] = b2; sm->cand[ixj] = a; }
                }
            }
            __syncthreads();
        }

    // -------- bitonic sort cutoff-bin values descending --------
    int n2p = 1; while (n2p < npb) n2p <<= 1;
    for (int i = npb + tid; i < n2p; i += NTH) sm->pbin[i] = -INFINITY;
    __syncthreads();
    for (int k = 2; k <= n2p; k <<= 1)
        for (int j = k >> 1; j > 0; j >>= 1) {
            for (int idx = tid; idx < n2p; idx += NTH) {
                int ixj = idx ^ j;
                if (ixj > idx) {
                    float a = sm->pbin[idx], b2 = sm->pbin[ixj];
                    bool up = ((idx & k) == 0);
                    if (up ? (a < b2) : (a > b2)) { sm->pbin[idx] = b2; sm->pbin[ixj] = a; }
                }
            }
            __syncthreads();
        }

    // -------- sampling over sorted candidates --------
    {
        int i0 = tid, i1 = tid + NTH;
        bool h0 = i0 < n2, h1 = i1 < n2;
        double e0v = 0.0, e1v = 0.0;
        if (h0 && i0 < C) e0v = exp((double)(unflipf((unsigned)(sm->cand[i0] >> 32)) - m));
        if (h1 && i1 < C) e1v = exp((double)(unflipf((unsigned)(sm->cand[i1] >> 32)) - m));
        __syncthreads();
        if (h0) { sm->bufA[i0] = e0v; sm->bufB[i0] = e0v; }
        if (h1) { sm->bufA[i1] = e1v; sm->bufB[i1] = e1v; }
        __syncthreads();
    }
    scan_inclusive(sm->bufA, n2);                 // inclusive cumsum of e
    const double ehead = sm->bufB[0];
    const double thrE  = (double)min_p * ehead;   // min-p threshold (exp units)
    // ---- apply filters (flat two-slot form, uniform barriers) ----
    {
        int i0 = tid, i1 = tid + NTH;
        bool h0 = i0 < n2, h1 = i1 < n2;
        double ps0 = 0.0, ps1 = 0.0;
        if (h0 && i0 < C) {
            double e = sm->bufB[i0];
            double cumex = sm->bufA[i0] - e;
            if (i0 < K && cumex <= P && e >= thrE) ps0 = e;
        }
        if (h1 && i1 < C) {
            double e = sm->bufB[i1];
            double cumex = sm->bufA[i1] - e;
            if (i1 < K && cumex <= P && e >= thrE) ps1 = e;
        }
        __syncthreads();
        if (h0) sm->bufA[i0] = ps0;
        if (h1) sm->bufA[i1] = ps1;
        __syncthreads();
    }
    scan_inclusive(sm->bufA, n2);                 // cdf of filtered ps
    const double total  = sm->bufA[n2 - 1];
    const double target = (double)u * total;
    {
        int cnt = 0;
        for (int idx = tid; idx < C; idx += NTH)
            if (sm->bufA[idx] < target) cnt++;
        if (cnt) atomicAdd(&sm->cntA, cnt);
    }
    __syncthreads();
    if (tid == 0) {
        int s = sm->cntA; if (s > C - 1) s = C - 1;
        unsigned long long key = sm->cand[s];
        sm->token = (int)(~(unsigned)(key & 0xFFFFFFFFull));
        sm->xtok  = unflipf((unsigned)(key >> 32));
        sm->cntA  = 0;                            // reset for refinement count
    }
    __syncthreads();

    // -------- top-p cutoff-bin refinement (exact threshold + kept mass) --------
    {
        int i0 = tid, i1 = tid + NTH;
        bool h0 = i0 < n2p, h1 = i1 < n2p;
        double e0v = 0.0, e1v = 0.0;
        if (h0 && i0 < npb) e0v = exp((double)(sm->pbin[i0] - m));
        if (h1 && i1 < npb) e1v = exp((double)(sm->pbin[i1] - m));
        __syncthreads();
        if (h0) { sm->bufA[i0] = e0v; sm->bufB[i0] = e0v; }
        if (h1) { sm->bufA[i1] = e1v; sm->bufB[i1] = e1v; }
        __syncthreads();
    }
    scan_inclusive(sm->bufA, n2p);
    {
        int cnt = 0;
        for (int idx = tid; idx < npb; idx += NTH) {
            double cumex = A_cbp + (sm->bufA[idx] - sm->bufB[idx]);
            if (cumex <= P) cnt++;
        }
        if (cnt) atomicAdd(&sm->cntA, cnt);
    }
    __syncthreads();
    if (tid == 0) {
        int t = sm->cntA;
        double S = A_cbp + (t > 0 ? sm->bufA[t - 1] : 0.0);
        sm->logS = (float)log(S);
        sm->xmin_kept = (t > 0) ? sm->pbin[t - 1] : INFINITY;
    }
    __syncthreads();
    const float logS = sm->logS;
    const float xmin = sm->xmin_kept;   // kept <=> x >= xmin (bin index monotone in x; t >= 1 always)

    // -------- pass 4: write logprobs (float4, threshold-only test) --------
    float4* __restrict__ lp_out4 =
        reinterpret_cast<float4*>(out + BB + (size_t)row * VV);
    for (int i = tid; i < VV4; i += NTH) {
        float4 v = rowp4[i];
        float x0 = v.x * invt, x1 = v.y * invt, x2 = v.z * invt, x3 = v.w * invt;
        float4 r;
        r.x = (x0 >= xmin) ? (x0 - m) - logS : FINFO_MIN;
        r.y = (x1 >= xmin) ? (x1 - m) - logS : FINFO_MIN;
        r.z = (x2 >= xmin) ? (x2 - m) - logS : FINFO_MIN;
        r.w = (x3 >= xmin) ? (x3 - m) - logS : FINFO_MIN;
        lp_out4[i] = r;
    }
    if (tid == 0) {
        out[row] = (float)sm->token;
        out[BB + (size_t)BB * VV + row] = (sm->xtok - m) - logS;
    }
}

extern "C" void kernel_launch(void* const* d_in, const int* in_sizes, int n_in,
                              void* d_out, int out_size)
{
    const float* logits = (const float*)d_in[0];
    const float* temps  = (const float*)d_in[1];
    const int*   topks  = (const int*)  d_in[2];
    const float* topps  = (const float*)d_in[3];
    const float* minps  = (const float*)d_in[4];
    const float* us     = (const float*)d_in[5];
    float* out = (float*)d_out;

    cudaFuncSetAttribute(sampler_kernel,
                         cudaFuncAttributeMaxDynamicSharedMemorySize,
                         (int)sizeof(Smem));
    sampler_kernel<<<BB, NTH, sizeof(Smem)>>>(logits, temps, topks, topps, minps, us, out);
}

// round 13
// speedup vs baseline: 1.2140x; 1.2140x over previous
#include <cuda_runtime.h>
#include <math.h>
#include <stdint.h>

#define BB 128
#define VV 128000
#define VV4 (VV / 4)
#define NBINS 8192
#define BPT (NBINS / NTH)         // 8 bins per thread
#define BIN_SCALE 256.0f          // bin width 1/256 over d = m - x
#define CAND_CAP 2048
#define NTH 1024
#define FINFO_MIN -3.4028234663852886e38f

#define CNT_SHIFT 47
#define MASK47 ((1ull << 47) - 1ull)
#define SCALE30 1073741824.0f     // 2^30
#define INV30 (1.0 / 1073741824.0)

struct Smem {
    unsigned long long  hist[NBINS];       // packed cnt<<47 | fix30(exp); becomes inclusive prefix
    unsigned long long  cand[CAND_CAP];    // top-k candidates: key = flip(x)<<32 | ~idx
    float               pbin[CAND_CAP];    // values in the top-p cutoff bin
    double              bufA[CAND_CAP];
    double              bufB[CAND_CAP];
    float               redf[32];
    // scalars
    int   cb_p, cb_k;
    unsigned int candCount, pbinCount;
    int   cntA;
    float logS;
    float xmin_kept;
    int   token;
    float xtok;
};

__device__ __forceinline__ unsigned flipf(float f) {
    unsigned u = __float_as_uint(f);
    return u ^ ((u >> 31) ? 0xFFFFFFFFu : 0x80000000u);
}
__device__ __forceinline__ float unflipf(unsigned u) {
    unsigned b = u ^ ((u & 0x80000000u) ? 0x80000000u : 0xFFFFFFFFu);
    return __uint_as_float(b);
}
__device__ __forceinline__ int binof(float d) {
    int b = (int)(d * BIN_SCALE);
    return b < 0 ? 0 : (b > NBINS - 1 ? NBINS - 1 : b);
}

// Inclusive double scan over a[0..n2), n2 = pow2 <= 2048, 2 elems/thread.
// shfl two-level scan: 3 barriers total. ALL NTH threads must call.
__device__ void scan_inclusive(double* a, int n2) {
    __shared__ double wd[32];
    int tid = threadIdx.x, lane = tid & 31, w = tid >> 5;
    int i0 = 2 * tid, i1 = i0 + 1;
    bool a0 = i0 < n2, a1 = i1 < n2;
    double e0 = a0 ? a[i0] : 0.0;
    double e1 = a1 ? a[i1] : 0.0;
    double s = e0 + e1;
#pragma unroll
    for (int o = 1; o < 32; o <<= 1) {
        double t = __shfl_up_sync(0xFFFFFFFFu, s, o);
        if (lane >= o) s += t;
    }
    if (lane == 31) wd[w] = s;
    __syncthreads();
    if (w == 0) {
        double v = wd[lane];
#pragma unroll
        for (int o = 1; o < 32; o <<= 1) {
            double t = __shfl_up_sync(0xFFFFFFFFu, v, o);
            if (lane >= o) v += t;
        }
        wd[lane] = v;
    }
    __syncthreads();
    double off = w ? wd[w - 1] : 0.0;
    double incl = off + s;            // inclusive through i1
    if (a1) a[i1] = incl;
    if (a0) a[i0] = incl - e1;
    __syncthreads();
}

__global__ void __launch_bounds__(NTH, 1)
sampler_kernel(const float* __restrict__ logits,
               const float* __restrict__ temps,
               const int*   __restrict__ topks,
               const float* __restrict__ topps,
               const float* __restrict__ minps,
               const float* __restrict__ us,
               float* __restrict__ out)
{
    extern __shared__ char smem_raw[];
    Smem* sm = reinterpret_cast<Smem*>(smem_raw);
    __shared__ unsigned long long wu[32];   // for the packed bin block-scan
    const int row = blockIdx.x;
    const int tid = threadIdx.x;
    const int lane = tid & 31;
    const int wid  = tid >> 5;
    const float* __restrict__ rowp = logits + (size_t)row * VV;
    const float4* __restrict__ rowp4 = reinterpret_cast<const float4*>(rowp);

    const float temp  = temps[row];
    const float invt  = 1.0f / temp;       // x = logit * invt, used identically in every pass
    const int   K     = topks[row];
    const float top_p = topps[row];
    const float min_p = minps[row];
    const float u     = us[row];

    // -------- init --------
    for (int i = tid; i < NBINS; i += NTH) sm->hist[i] = 0ull;
    if (tid == 0) {
        sm->candCount = 0u; sm->pbinCount = 0u; sm->cntA = 0;
        sm->cb_p = NBINS - 1; sm->cb_k = NBINS - 1;
    }

    // -------- pass 1: max over raw logits (prefetched) --------
    float mt = -INFINITY;
    {
        float4 v = rowp4[tid];             // tid < 1024 < VV4 always
        for (int i = tid; i < VV4; ) {
            float4 cur = v;
            int nx = i + NTH;
            if (nx < VV4) v = rowp4[nx];
            mt = fmaxf(mt, fmaxf(fmaxf(cur.x, cur.y), fmaxf(cur.z, cur.w)));
            i = nx;
        }
    }
#pragma unroll
    for (int o = 16; o > 0; o >>= 1) mt = fmaxf(mt, __shfl_xor_sync(0xFFFFFFFFu, mt, o));
    if (lane == 0) sm->redf[wid] = mt;
    __syncthreads();
    if (tid < 32) {
        float v = sm->redf[tid];
#pragma unroll
        for (int o = 16; o > 0; o >>= 1) v = fmaxf(v, __shfl_xor_sync(0xFFFFFFFFu, v, o));
        if (tid == 0) sm->redf[0] = v;
    }
    __syncthreads();
    const float m = sm->redf[0] * invt;
    __syncthreads();

    // -------- pass 2: packed histogram over d = m - x (prefetched) --------
    {
        float4 v = rowp4[tid];
        for (int i = tid; i < VV4; ) {
            float4 cur = v;
            int nx = i + NTH;
            if (nx < VV4) v = rowp4[nx];
            float d0 = m - cur.x * invt, d1 = m - cur.y * invt;
            float d2 = m - cur.z * invt, d3 = m - cur.w * invt;
            float e0 = __expf(-d0), e1 = __expf(-d1), e2 = __expf(-d2), e3 = __expf(-d3);
            int b0 = binof(d0), b1 = binof(d1), b2 = binof(d2), b3 = binof(d3);
            atomicAdd(&sm->hist[b0], (1ull << CNT_SHIFT) + (unsigned long long)(e0 * SCALE30 + 0.5f));
            atomicAdd(&sm->hist[b1], (1ull << CNT_SHIFT) + (unsigned long long)(e1 * SCALE30 + 0.5f));
            atomicAdd(&sm->hist[b2], (1ull << CNT_SHIFT) + (unsigned long long)(e2 * SCALE30 + 0.5f));
            atomicAdd(&sm->hist[b3], (1ull << CNT_SHIFT) + (unsigned long long)(e3 * SCALE30 + 0.5f));
            i = nx;
        }
    }
    __syncthreads();

    // -------- packed prefix scan over bins (8 bins/thread; shfl block scan, exact u64) --------
    const int base = tid * BPT;
    unsigned long long lh[BPT];
    unsigned long long hrun = 0ull;
#pragma unroll
    for (int j = 0; j < BPT; j++) {
        hrun += sm->hist[base + j];  lh[j] = hrun;
    }
    {
        unsigned long long s = hrun;
#pragma unroll
        for (int o = 1; o < 32; o <<= 1) {
            unsigned long long t = __shfl_up_sync(0xFFFFFFFFu, s, o);
            if (lane >= o) s += t;
        }
        if (lane == 31) wu[wid] = s;
        __syncthreads();
        if (wid == 0) {
            unsigned long long v = wu[lane];
#pragma unroll
            for (int o = 1; o < 32; o <<= 1) {
                unsigned long long t = __shfl_up_sync(0xFFFFFFFFu, v, o);
                if (lane >= o) v += t;
            }
            wu[lane] = v;
        }
        __syncthreads();
        unsigned long long incl = (wid ? wu[wid - 1] : 0ull) + s;   // inclusive prefix of thread totals
        unsigned long long hex = incl - hrun;                        // exclusive before this thread's bins
#pragma unroll
        for (int j = 0; j < BPT; j++)
            sm->hist[base + j] = lh[j] + hex;                        // inclusive packed prefix
    }
    __syncthreads();

    const double Zh = (double)(sm->hist[NBINS - 1] & MASK47) * INV30;
    const double P  = (double)top_p * Zh;              // top-p mass threshold (exp units)

    // -------- locate cutoff bins --------
#pragma unroll
    for (int j = 0; j < BPT; j++) {
        int g = base + j;
        unsigned long long Au = g ? sm->hist[g - 1] : 0ull;
        unsigned long long Iu = sm->hist[g];
        double A = (double)(Au & MASK47) * INV30;
        double I = (double)(Iu & MASK47) * INV30;
        if (A <= P && P < I) sm->cb_p = g;
        unsigned cA = (unsigned)(Au >> CNT_SHIFT);
        unsigned cI = (unsigned)(Iu >> CNT_SHIFT);
        if (cA < (unsigned)K && (unsigned)K <= cI) sm->cb_k = g;
    }
    __syncthreads();
    const int    cb_p  = sm->cb_p;
    const int    cb_k  = sm->cb_k;
    const double A_cbp = cb_p ? (double)(sm->hist[cb_p - 1] & MASK47) * INV30 : 0.0;

    // -------- pass 3: collect top-k candidates and top-p cutoff-bin members (prefetched) --------
    {
        float4 v = rowp4[tid];
        for (int i = tid; i < VV4; ) {
            float4 cur = v;
            int nx = i + NTH;
            if (nx < VV4) v = rowp4[nx];
            float xs[4];
            xs[0] = cur.x * invt; xs[1] = cur.y * invt; xs[2] = cur.z * invt; xs[3] = cur.w * invt;
#pragma unroll
            for (int j = 0; j < 4; j++) {
                float x = xs[j];
                int b = binof(m - x);
                if (b <= cb_k) {
                    unsigned p = atomicAdd(&sm->candCount, 1u);
                    if (p < CAND_CAP) {
                        unsigned fu = flipf(x);
                        unsigned gidx = (unsigned)(4 * i + j);
                        sm->cand[p] = ((unsigned long long)fu << 32) | (unsigned)(~gidx);
                    }
                }
                if (b == cb_p) {
                    unsigned q = atomicAdd(&sm->pbinCount, 1u);
                    if (q < CAND_CAP) sm->pbin[q] = x;
                }
            }
            i = nx;
        }
    }
    __syncthreads();
    const int C   = (int)min(sm->candCount, (unsigned)CAND_CAP);
    const int npb = (int)min(sm->pbinCount, (unsigned)CAND_CAP);

    // -------- bitonic sort candidates descending (pair-mapped: no wasted threads) --------
    int n2 = 1; while (n2 < C) n2 <<= 1;
    for (int i = C + tid; i < n2; i += NTH) sm->cand[i] = 0ull;
    __syncthreads();
    for (int k = 2; k <= n2; k <<= 1)
        for (int j = k >> 1; j > 0; j >>= 1) {
            for (int t = tid; t < (n2 >> 1); t += NTH) {
                int i = ((t & ~(j - 1)) << 1) | (t & (j - 1));
                int p = i | j;
                unsigned long long a = sm->cand[i], b2 = sm->cand[p];
                bool up = ((i & k) == 0);
                if (up ? (a < b2) : (a > b2)) { sm->cand[i] = b2; sm->cand[p] = a; }
            }
            __syncthreads();
        }

    // -------- bitonic sort cutoff-bin values descending (pair-mapped) --------
    int n2p = 1; while (n2p < npb) n2p <<= 1;
    for (int i = npb + tid; i < n2p; i += NTH) sm->pbin[i] = -INFINITY;
    __syncthreads();
    for (int k = 2; k <= n2p; k <<= 1)
        for (int j = k >> 1; j > 0; j >>= 1) {
            for (int t = tid; t < (n2p >> 1); t += NTH) {
                int i = ((t & ~(j - 1)) << 1) | (t & (j - 1));
                int p = i | j;
                float a = sm->pbin[i], b2 = sm->pbin[p];
                bool up = ((i & k) == 0);
                if (up ? (a < b2) : (a > b2)) { sm->pbin[i] = b2; sm->pbin[p] = a; }
            }
            __syncthreads();
        }

    // -------- sampling over sorted candidates --------
    {
        int i0 = tid, i1 = tid + NTH;
        bool h0 = i0 < n2, h1 = i1 < n2;
        double e0v = 0.0, e1v = 0.0;
        if (h0 && i0 < C) e0v = exp((double)(unflipf((unsigned)(sm->cand[i0] >> 32)) - m));
        if (h1 && i1 < C) e1v = exp((double)(unflipf((unsigned)(sm->cand[i1] >> 32)) - m));
        __syncthreads();
        if (h0) { sm->bufA[i0] = e0v; sm->bufB[i0] = e0v; }
        if (h1) { sm->bufA[i1] = e1v; sm->bufB[i1] = e1v; }
        __syncthreads();
    }
    scan_inclusive(sm->bufA, n2);                 // inclusive cumsum of e
    const double ehead = sm->bufB[0];
    const double thrE  = (double)min_p * ehead;   // min-p threshold (exp units)
    // ---- apply filters (flat two-slot form, uniform barriers) ----
    {
        int i0 = tid, i1 = tid + NTH;
        bool h0 = i0 < n2, h1 = i1 < n2;
        double ps0 = 0.0, ps1 = 0.0;
        if (h0 && i0 < C) {
            double e = sm->bufB[i0];
            double cumex = sm->bufA[i0] - e;
            if (i0 < K && cumex <= P && e >= thrE) ps0 = e;
        }
        if (h1 && i1 < C) {
            double e = sm->bufB[i1];
            double cumex = sm->bufA[i1] - e;
            if (i1 < K && cumex <= P && e >= thrE) ps1 = e;
        }
        __syncthreads();
        if (h0) sm->bufA[i0] = ps0;
        if (h1) sm->bufA[i1] = ps1;
        __syncthreads();
    }
    scan_inclusive(sm->bufA, n2);                 // cdf of filtered ps
    const double total  = sm->bufA[n2 - 1];
    const double target = (double)u * total;
    {
        int cnt = 0;
        for (int idx = tid; idx < C; idx += NTH)
            if (sm->bufA[idx] < target) cnt++;
        if (cnt) atomicAdd(&sm->cntA, cnt);
    }
    __syncthreads();
    if (tid == 0) {
        int s = sm->cntA; if (s > C - 1) s = C - 1;
        unsigned long long key = sm->cand[s];
        sm->token = (int)(~(unsigned)(key & 0xFFFFFFFFull));
        sm->xtok  = unflipf((unsigned)(key >> 32));
        sm->cntA  = 0;                            // reset for refinement count
    }
    __syncthreads();

    // -------- top-p cutoff-bin refinement (exact threshold + kept mass) --------
    {
        int i0 = tid, i1 = tid + NTH;
        bool h0 = i0 < n2p, h1 = i1 < n2p;
        double e0v = 0.0, e1v = 0.0;
        if (h0 && i0 < npb) e0v = exp((double)(sm->pbin[i0] - m));
        if (h1 && i1 < npb) e1v = exp((double)(sm->pbin[i1] - m));
        __syncthreads();
        if (h0) { sm->bufA[i0] = e0v; sm->bufB[i0] = e0v; }
        if (h1) { sm->bufA[i1] = e1v; sm->bufB[i1] = e1v; }
        __syncthreads();
    }
    scan_inclusive(sm->bufA, n2p);
    {
        int cnt = 0;
        for (int idx = tid; idx < npb; idx += NTH) {
            double cumex = A_cbp + (sm->bufA[idx] - sm->bufB[idx]);
            if (cumex <= P) cnt++;
        }
        if (cnt) atomicAdd(&sm->cntA, cnt);
    }
    __syncthreads();
    if (tid == 0) {
        int t = sm->cntA;
        double S = A_cbp + (t > 0 ? sm->bufA[t - 1] : 0.0);
        sm->logS = (float)log(S);
        sm->xmin_kept = (t > 0) ? sm->pbin[t - 1] : INFINITY;
    }
    __syncthreads();
    const float logS = sm->logS;
    const float xmin = sm->xmin_kept;   // kept <=> x >= xmin (bin index monotone in x; t >= 1 always)

    // -------- pass 4: write logprobs (prefetched, threshold-only test) --------
    float4* __restrict__ lp_out4 =
        reinterpret_cast<float4*>(out + BB + (size_t)row * VV);
    {
        float4 v = rowp4[tid];
        for (int i = tid; i < VV4; ) {
            float4 cur = v;
            int nx = i + NTH;
            if (nx < VV4) v = rowp4[nx];
            float x0 = cur.x * invt, x1 = cur.y * invt, x2 = cur.z * invt, x3 = cur.w * invt;
            float4 r;
            r.x = (x0 >= xmin) ? (x0 - m) - logS : FINFO_MIN;
            r.y = (x1 >= xmin) ? (x1 - m) - logS : FINFO_MIN;
            r.z = (x2 >= xmin) ? (x2 - m) - logS : FINFO_MIN;
            r.w = (x3 >= xmin) ? (x3 - m) - logS : FINFO_MIN;
            lp_out4[i] = r;
            i = nx;
        }
    }
    if (tid == 0) {
        out[row] = (float)sm->token;
        out[BB + (size_t)BB * VV + row] = (sm->xtok - m) - logS;
    }
}

extern "C" void kernel_launch(void* const* d_in, const int* in_sizes, int n_in,
                              void* d_out, int out_size)
{
    const float* logits = (const float*)d_in[0];
    const float* temps  = (const float*)d_in[1];
    const int*   topks  = (const int*)  d_in[2];
    const float* topps  = (const float*)d_in[3];
    const float* minps  = (const float*)d_in[4];
    const float* us     = (const float*)d_in[5];
    float* out = (float*)d_out;

    cudaFuncSetAttribute(sampler_kernel,
                         cudaFuncAttributeMaxDynamicSharedMemorySize,
                         (int)sizeof(Smem));
    sampler_kernel<<<BB, NTH, sizeof(Smem)>>>(logits, temps, topks, topps, minps, us, out);
}